// round 1
// baseline (speedup 1.0000x reference)
#include <cuda_runtime.h>

#define D   256
#define NB  30
#define EG  240
#define BG  2048

// Precomputed folded input-MLP matrices
__device__ float g_Mgeo[5 * D];    // W_geo @ W_lot[0:256]
__device__ float g_Msem[11 * D];   // emb   @ W_lot[256:512]
__device__ float g_bias0[D];       // b_geo @ W_lot[0:256] + b_lot

// ---------------------------------------------------------------------------
// Precompute kernel: tiny folded GEMMs (runs once per launch, ~microseconds)
// ---------------------------------------------------------------------------
__global__ void pre_kernel(const float* __restrict__ Wgeo,  // [5,256]
                           const float* __restrict__ bgeo,  // [256]
                           const float* __restrict__ emb,   // [11,256]
                           const float* __restrict__ Wlot,  // [542,256]
                           const float* __restrict__ blot)  // [256]
{
    int c = threadIdx.x;
    int r = blockIdx.x;
    if (r < 5) {
        float a = 0.f;
        for (int j = 0; j < D; j++) a += Wgeo[r * D + j] * Wlot[j * D + c];
        g_Mgeo[r * D + c] = a;
    } else if (r < 16) {
        int s = r - 5;
        float a = 0.f;
        for (int j = 0; j < D; j++) a += emb[s * D + j] * Wlot[(D + j) * D + c];
        g_Msem[s * D + c] = a;
    } else {
        float a = blot[c];
        for (int j = 0; j < D; j++) a += bgeo[j] * Wlot[j * D + c];
        g_bias0[c] = a;
    }
}

// ---------------------------------------------------------------------------
// Main kernel: one CTA per graph. 256 threads; thread t owns channel c = t.
// smem: h[30][256], xa[30][256] (neighbor mean), plus small per-graph data.
// ---------------------------------------------------------------------------
__global__ void __launch_bounds__(256)
graph_kernel(const float* __restrict__ geometry,  // [N,5]
             const int*   __restrict__ semantic,  // [N]
             const int*   __restrict__ e_src,     // [E]
             const int*   __restrict__ e_dst,     // [E]
             const float* __restrict__ Wlot,      // [542,256] (rows 512.. = pos)
             const float* __restrict__ Wmp1, const float* __restrict__ bmp1,
             const float* __restrict__ Wmp2, const float* __restrict__ bmp2,
             const float* __restrict__ Wmp3, const float* __restrict__ bmp3,
             const float* __restrict__ Wagg, const float* __restrict__ bagg,
             const float* __restrict__ Wmu,  const float* __restrict__ bmu,
             const float* __restrict__ Wvar, const float* __restrict__ bvar,
             float* __restrict__ out)
{
    extern __shared__ float smem[];
    float* sh_h  = smem;                 // NB*D = 7680 floats
    float* sh_xa = smem + NB * D;        // NB*D
    float* s_geo = smem + 2 * NB * D;    // NB*5
    float* s_inv = s_geo + NB * 5;       // NB
    int*   s_sem = (int*)(s_inv + NB);   // NB
    int*   s_src = s_sem + NB;           // EG
    int*   s_dst = s_src + EG;           // EG
    int*   s_cnt = s_dst + EG;           // NB

    const int g = blockIdx.x;
    const int c = threadIdx.x;

    // ---- load per-graph data ----
    for (int i = c; i < NB * 5; i += 256) s_geo[i] = geometry[g * NB * 5 + i];
    for (int i = c; i < NB; i += 256) { s_sem[i] = semantic[g * NB + i]; s_cnt[i] = 0; }
    __syncthreads();
    if (c < EG) {
        int s = e_src[g * EG + c] - g * NB;
        int d = e_dst[g * EG + c] - g * NB;
        s_src[c] = s;
        s_dst[c] = d;
        atomicAdd(&s_cnt[d], 1);
    }
    __syncthreads();
    if (c < NB) s_inv[c] = s_cnt[c] > 0 ? 1.0f / (float)s_cnt[c] : 0.0f;

    // ---- h0 = relu(geo@Mgeo + Msem[sem] + W_lot_pos[n] + bias0) ----
    float mg[5];
    #pragma unroll
    for (int i = 0; i < 5; i++) mg[i] = g_Mgeo[i * D + c];
    const float bias0 = g_bias0[c];
    float g0 = 0.f;
    for (int n = 0; n < NB; n++) {
        float v = bias0 + Wlot[(2 * D + n) * D + c] + g_Msem[s_sem[n] * D + c];
        #pragma unroll
        for (int i = 0; i < 5; i++) v += s_geo[n * 5 + i] * mg[i];
        v = fmaxf(v, 0.f);
        sh_h[n * D + c] = v;
        g0 = fmaxf(g0, v);
    }
    __syncthreads();

    // ---- 3 message-passing layers ----
    const float* Wmps[3] = {Wmp1, Wmp2, Wmp3};
    const float* bmps[3] = {bmp1, bmp2, bmp3};
    float gmax[3];

    for (int l = 0; l < 3; l++) {
        // zero the aggregation buffer
        for (int i = c; i < NB * D; i += 256) sh_xa[i] = 0.f;
        __syncthreads();

        // scatter-add over edges: thread c owns column c -> race-free
        for (int e = 0; e < EG; e++) {
            int s = s_src[e], d = s_dst[e];
            sh_xa[d * D + c] += sh_h[s * D + c];
        }
        __syncthreads();

        // mean
        for (int i = c; i < NB * D; i += 256) sh_xa[i] *= s_inv[i >> 8];
        __syncthreads();

        // GEMM: acc[n] = b + sum_k h[n][k]*W1[k][c] + xa[n][k]*W2[k][c]
        const float* W1 = Wmps[l];
        const float* W2 = Wmps[l] + D * D;
        const float  bm = bmps[l][c];
        float acc[NB];
        #pragma unroll
        for (int n = 0; n < NB; n++) acc[n] = bm;

        for (int k4 = 0; k4 < D; k4 += 4) {
            float w10 = W1[(k4 + 0) * D + c], w11 = W1[(k4 + 1) * D + c];
            float w12 = W1[(k4 + 2) * D + c], w13 = W1[(k4 + 3) * D + c];
            float w20 = W2[(k4 + 0) * D + c], w21 = W2[(k4 + 1) * D + c];
            float w22 = W2[(k4 + 2) * D + c], w23 = W2[(k4 + 3) * D + c];
            #pragma unroll
            for (int n = 0; n < NB; n++) {
                float4 hv = *(const float4*)(sh_h + n * D + k4);
                float4 av = *(const float4*)(sh_xa + n * D + k4);
                acc[n] += hv.x * w10 + hv.y * w11 + hv.z * w12 + hv.w * w13
                        + av.x * w20 + av.y * w21 + av.z * w22 + av.w * w23;
            }
        }
        __syncthreads();  // all reads of sh_h / sh_xa complete

        float gm = 0.f;
        #pragma unroll
        for (int n = 0; n < NB; n++) {
            float v = (s_cnt[n] > 0) ? fmaxf(acc[n], 0.f) : 0.f;  // cnt=0 -> 0
            sh_h[n * D + c] = v;
            gm = fmaxf(gm, v);
        }
        gmax[l] = gm;
        __syncthreads();
    }

    // ---- readout: g = [g0|g1|g2|g3], latent = g@Wagg+b, mu/logvar ----
    sh_xa[0 * D + c] = g0;
    sh_xa[1 * D + c] = gmax[0];
    sh_xa[2 * D + c] = gmax[1];
    sh_xa[3 * D + c] = gmax[2];
    __syncthreads();

    float lat = bagg[c];
    for (int j4 = 0; j4 < 4 * D; j4 += 4) {
        float4 gv = *(const float4*)(sh_xa + j4);
        lat += gv.x * Wagg[(j4 + 0) * D + c] + gv.y * Wagg[(j4 + 1) * D + c]
             + gv.z * Wagg[(j4 + 2) * D + c] + gv.w * Wagg[(j4 + 3) * D + c];
    }
    sh_h[c] = lat;
    __syncthreads();

    float mu = bmu[c], lv = bvar[c];
    for (int j4 = 0; j4 < D; j4 += 4) {
        float4 L = *(const float4*)(sh_h + j4);
        mu += L.x * Wmu[(j4 + 0) * D + c] + L.y * Wmu[(j4 + 1) * D + c]
            + L.z * Wmu[(j4 + 2) * D + c] + L.w * Wmu[(j4 + 3) * D + c];
        lv += L.x * Wvar[(j4 + 0) * D + c] + L.y * Wvar[(j4 + 1) * D + c]
            + L.z * Wvar[(j4 + 2) * D + c] + L.w * Wvar[(j4 + 3) * D + c];
    }
    out[g * D + c]          = mu;   // mu block
    out[BG * D + g * D + c] = lv;   // log_var block
}

// ---------------------------------------------------------------------------
extern "C" void kernel_launch(void* const* d_in, const int* in_sizes, int n_in,
                              void* d_out, int out_size)
{
    const float* geometry = (const float*)d_in[0];
    const int*   semantic = (const int*)d_in[1];
    const int*   eidx     = (const int*)d_in[2];
    // d_in[3] = batch (implicit from node index, unused)
    const float* Wgeo = (const float*)d_in[4];
    const float* bgeo = (const float*)d_in[5];
    const float* emb  = (const float*)d_in[6];
    const float* Wlot = (const float*)d_in[7];
    const float* blot = (const float*)d_in[8];
    const float* Wmp1 = (const float*)d_in[9];
    const float* bmp1 = (const float*)d_in[10];
    const float* Wmp2 = (const float*)d_in[11];
    const float* bmp2 = (const float*)d_in[12];
    const float* Wmp3 = (const float*)d_in[13];
    const float* bmp3 = (const float*)d_in[14];
    const float* Wagg = (const float*)d_in[15];
    const float* bagg = (const float*)d_in[16];
    const float* Wmu  = (const float*)d_in[17];
    const float* bmu  = (const float*)d_in[18];
    const float* Wvar = (const float*)d_in[19];
    const float* bvar = (const float*)d_in[20];

    const int n_edges = in_sizes[2] / 2;
    const int* e_src = eidx;
    const int* e_dst = eidx + n_edges;

    pre_kernel<<<17, 256>>>(Wgeo, bgeo, emb, Wlot, blot);

    // smem: 2*NB*D + NB*5 + NB floats, plus (NB + 2*EG + NB) ints
    size_t smem_bytes = (2 * NB * D + NB * 5 + NB) * sizeof(float)
                      + (NB + 2 * EG + NB) * sizeof(int);
    cudaFuncSetAttribute(graph_kernel, cudaFuncAttributeMaxDynamicSharedMemorySize,
                         (int)smem_bytes);

    graph_kernel<<<BG, 256, smem_bytes>>>(
        geometry, semantic, e_src, e_dst, Wlot,
        Wmp1, bmp1, Wmp2, bmp2, Wmp3, bmp3,
        Wagg, bagg, Wmu, bmu, Wvar, bvar,
        (float*)d_out);
}